// round 6
// baseline (speedup 1.0000x reference)
#include <cuda_runtime.h>

// 9-DoF alignment, one WARP per batch (no smem, no barriers).
//   cov = (x-mu_x)^T (y-mu_y); R = polar_rotation(cov) (== U V^T, incl. sign)
//   t = mu_y - R mu_x; S = ||yc||_F / (||xc||_F + 1e-6)
// Lane l handles 32 points: 8 groups x (3 consecutive float4 = 4 points),
// with depth-2 software pipelining (prefetch next group's 6 loads before
// consuming the current group) to double per-warp MLP.

__global__ __launch_bounds__(256)
void align9dof_kernel(const float* __restrict__ x,
                      const float* __restrict__ mu_x,
                      const float* __restrict__ y,
                      const float* __restrict__ mu_y,
                      float* __restrict__ out,
                      int B)
{
    const int warp = threadIdx.x >> 5;
    const int lane = threadIdx.x & 31;
    const int b    = blockIdx.x * 8 + warp;
    if (b >= B) return;

    // Per-batch means (uniform broadcast loads)
    const float mx0 = mu_x[b * 3 + 0];
    const float mx1 = mu_x[b * 3 + 1];
    const float mx2 = mu_x[b * 3 + 2];
    const float my0 = mu_y[b * 3 + 0];
    const float my1 = mu_y[b * 3 + 1];
    const float my2 = mu_y[b * 3 + 2];

    const float4* __restrict__ xb = (const float4*)(x + (size_t)b * 3072);
    const float4* __restrict__ yb = (const float4*)(y + (size_t)b * 3072);

    const int base = 3 * lane;

    // Prologue: group 0 loads
    float4 px0 = __ldcs(&xb[base + 0]);
    float4 px1 = __ldcs(&xb[base + 1]);
    float4 px2 = __ldcs(&xb[base + 2]);
    float4 py0 = __ldcs(&yb[base + 0]);
    float4 py1 = __ldcs(&yb[base + 1]);
    float4 py2 = __ldcs(&yb[base + 2]);

    float v[11];  // c00..c22, sxx, syy
#pragma unroll
    for (int i = 0; i < 11; i++) v[i] = 0.0f;

#pragma unroll
    for (int g = 0; g < 8; g++) {
        // Hold current group
        const float4 ax0 = px0, ax1 = px1, ax2 = px2;
        const float4 ay0 = py0, ay1 = py1, ay2 = py2;

        // Prefetch next group before consuming (depth-2 pipeline)
        if (g < 7) {
            const int nb = (g + 1) * 96 + base;
            px0 = __ldcs(&xb[nb + 0]);
            px1 = __ldcs(&xb[nb + 1]);
            px2 = __ldcs(&xb[nb + 2]);
            py0 = __ldcs(&yb[nb + 0]);
            py1 = __ldcs(&yb[nb + 1]);
            py2 = __ldcs(&yb[nb + 2]);
        }

        const float px[4][3] = {{ax0.x, ax0.y, ax0.z}, {ax0.w, ax1.x, ax1.y},
                                {ax1.z, ax1.w, ax2.x}, {ax2.y, ax2.z, ax2.w}};
        const float py[4][3] = {{ay0.x, ay0.y, ay0.z}, {ay0.w, ay1.x, ay1.y},
                                {ay1.z, ay1.w, ay2.x}, {ay2.y, ay2.z, ay2.w}};

#pragma unroll
        for (int p = 0; p < 4; p++) {
            const float u0 = px[p][0] - mx0, u1 = px[p][1] - mx1, u2 = px[p][2] - mx2;
            const float w0 = py[p][0] - my0, w1 = py[p][1] - my1, w2 = py[p][2] - my2;
            v[0] = fmaf(u0, w0, v[0]); v[1] = fmaf(u0, w1, v[1]); v[2] = fmaf(u0, w2, v[2]);
            v[3] = fmaf(u1, w0, v[3]); v[4] = fmaf(u1, w1, v[4]); v[5] = fmaf(u1, w2, v[5]);
            v[6] = fmaf(u2, w0, v[6]); v[7] = fmaf(u2, w1, v[7]); v[8] = fmaf(u2, w2, v[8]);
            v[9]  = fmaf(u0, u0, fmaf(u1, u1, fmaf(u2, u2, v[9])));
            v[10] = fmaf(w0, w0, fmaf(w1, w1, fmaf(w2, w2, v[10])));
        }
    }

    // Warp butterfly reduction: all lanes end with the full batch sums
#pragma unroll
    for (int off = 16; off > 0; off >>= 1) {
#pragma unroll
        for (int i = 0; i < 11; i++)
            v[i] += __shfl_xor_sync(0xFFFFFFFFu, v[i], off);
    }

    // ---- Polar factor via determinant-scaled Newton (all lanes, redundant) ----
    float fro2 = 0.0f;
#pragma unroll
    for (int i = 0; i < 9; i++) fro2 = fmaf(v[i], v[i], fro2);
    const float invf = rsqrtf(fmaxf(fro2, 1e-30f));

    float X[9];
#pragma unroll
    for (int i = 0; i < 9; i++) X[i] = v[i] * invf;

#pragma unroll
    for (int it = 0; it < 8; it++) {
        float C[9];  // cofactor matrix: X^{-T} = C / det
        C[0] = X[4] * X[8] - X[5] * X[7];
        C[1] = X[5] * X[6] - X[3] * X[8];
        C[2] = X[3] * X[7] - X[4] * X[6];
        C[3] = X[2] * X[7] - X[1] * X[8];
        C[4] = X[0] * X[8] - X[2] * X[6];
        C[5] = X[1] * X[6] - X[0] * X[7];
        C[6] = X[1] * X[5] - X[2] * X[4];
        C[7] = X[2] * X[3] - X[0] * X[5];
        C[8] = X[0] * X[4] - X[1] * X[3];
        float det = X[0] * C[0] + X[1] * C[1] + X[2] * C[2];
        float ad  = fmaxf(fabsf(det), 1e-30f);
        float eta = rcbrtf(ad);            // |det|^{-1/3}
        float k1  = 0.5f * eta;
        float k2  = 0.5f / (eta * det);    // keeps det's sign
#pragma unroll
        for (int i = 0; i < 9; i++) X[i] = k1 * X[i] + k2 * C[i];
    }

    // t = mu_y - R mu_x
    const float t0 = my0 - (X[0] * mx0 + X[1] * mx1 + X[2] * mx2);
    const float t1 = my1 - (X[3] * mx0 + X[4] * mx1 + X[5] * mx2);
    const float t2 = my2 - (X[6] * mx0 + X[7] * mx1 + X[8] * mx2);

    const float sf = sqrtf(v[10]) / (sqrtf(v[9]) + 1e-6f);

    // ---- Coalesced predicated stores (select-chains, no reg-indexed arrays) ----
    if (lane < 9) {
        float r = (lane == 0) ? X[0] :
                  (lane == 1) ? X[1] :
                  (lane == 2) ? X[2] :
                  (lane == 3) ? X[3] :
                  (lane == 4) ? X[4] :
                  (lane == 5) ? X[5] :
                  (lane == 6) ? X[6] :
                  (lane == 7) ? X[7] : X[8];
        out[(size_t)b * 9 + lane] = r;
    }
    if (lane < 3) {
        float tv = (lane == 0) ? t0 : (lane == 1) ? t1 : t2;
        out[(size_t)B * 9 + (size_t)b * 3 + lane] = tv;
    }
    if (lane == 0) {
        out[(size_t)B * 12 + b] = sf;
    }
}

extern "C" void kernel_launch(void* const* d_in, const int* in_sizes, int n_in,
                              void* d_out, int out_size)
{
    const float* x    = (const float*)d_in[0];
    const float* mu_x = (const float*)d_in[1];
    const float* y    = (const float*)d_in[2];
    const float* mu_y = (const float*)d_in[3];
    float* out        = (float*)d_out;

    const int B = in_sizes[1] / 3;  // mu_x is [B,3]

    align9dof_kernel<<<(B + 7) / 8, 256>>>(x, mu_x, y, mu_y, out, B);
}

// round 7
// speedup vs baseline: 1.0065x; 1.0065x over previous
#include <cuda_runtime.h>

// 9-DoF alignment, one WARP per batch (no smem, no barriers).
//   cov = (x-mu_x)^T (y-mu_y); R = polar_rotation(cov) (== U V^T, incl. sign)
//   t = mu_y - R mu_x; S = ||yc||_F / (||xc||_F + 1e-6)
//
// Lane l handles 32 points: 8 groups x (3 consecutive float4 = 4 points).
// Depth-3 software pipeline with a 3-slot rotation buffer: groups g+1, g+2
// are in flight (12 outstanding LDG.128) while group g is consumed.
// __launch_bounds__(256, 2) raises the ptxas register budget (~128) so the
// pipeline's live registers are not compacted away (R6 failure mode).

__global__ __launch_bounds__(256, 2)
void align9dof_kernel(const float* __restrict__ x,
                      const float* __restrict__ mu_x,
                      const float* __restrict__ y,
                      const float* __restrict__ mu_y,
                      float* __restrict__ out,
                      int B)
{
    const int warp = threadIdx.x >> 5;
    const int lane = threadIdx.x & 31;
    const int b    = blockIdx.x * 8 + warp;
    if (b >= B) return;

    // Per-batch means (uniform broadcast loads)
    const float mx0 = mu_x[b * 3 + 0];
    const float mx1 = mu_x[b * 3 + 1];
    const float mx2 = mu_x[b * 3 + 2];
    const float my0 = mu_y[b * 3 + 0];
    const float my1 = mu_y[b * 3 + 1];
    const float my2 = mu_y[b * 3 + 2];

    const float4* __restrict__ xb = (const float4*)(x + (size_t)b * 3072);
    const float4* __restrict__ yb = (const float4*)(y + (size_t)b * 3072);

    const int base = 3 * lane;

    // 3-slot rotation buffers (fully unrolled -> register-resident)
    float4 bx[3][3];
    float4 by[3][3];

    // Prologue: groups 0 and 1 in flight
#pragma unroll
    for (int s = 0; s < 2; s++) {
        const int gb = s * 96 + base;
        bx[s][0] = __ldcs(&xb[gb + 0]);
        bx[s][1] = __ldcs(&xb[gb + 1]);
        bx[s][2] = __ldcs(&xb[gb + 2]);
        by[s][0] = __ldcs(&yb[gb + 0]);
        by[s][1] = __ldcs(&yb[gb + 1]);
        by[s][2] = __ldcs(&yb[gb + 2]);
    }

    float v[11];  // c00..c22, sxx, syy
#pragma unroll
    for (int i = 0; i < 11; i++) v[i] = 0.0f;

#pragma unroll
    for (int g = 0; g < 8; g++) {
        // Prefetch group g+2 into the slot being retired (depth-3 pipeline)
        if (g < 6) {
            const int s  = (g + 2) % 3;
            const int gb = (g + 2) * 96 + base;
            bx[s][0] = __ldcs(&xb[gb + 0]);
            bx[s][1] = __ldcs(&xb[gb + 1]);
            bx[s][2] = __ldcs(&xb[gb + 2]);
            by[s][0] = __ldcs(&yb[gb + 0]);
            by[s][1] = __ldcs(&yb[gb + 1]);
            by[s][2] = __ldcs(&yb[gb + 2]);
        }

        const int c = g % 3;
        const float4 ax0 = bx[c][0], ax1 = bx[c][1], ax2 = bx[c][2];
        const float4 ay0 = by[c][0], ay1 = by[c][1], ay2 = by[c][2];

        const float px[4][3] = {{ax0.x, ax0.y, ax0.z}, {ax0.w, ax1.x, ax1.y},
                                {ax1.z, ax1.w, ax2.x}, {ax2.y, ax2.z, ax2.w}};
        const float py[4][3] = {{ay0.x, ay0.y, ay0.z}, {ay0.w, ay1.x, ay1.y},
                                {ay1.z, ay1.w, ay2.x}, {ay2.y, ay2.z, ay2.w}};

#pragma unroll
        for (int p = 0; p < 4; p++) {
            const float u0 = px[p][0] - mx0, u1 = px[p][1] - mx1, u2 = px[p][2] - mx2;
            const float w0 = py[p][0] - my0, w1 = py[p][1] - my1, w2 = py[p][2] - my2;
            v[0] = fmaf(u0, w0, v[0]); v[1] = fmaf(u0, w1, v[1]); v[2] = fmaf(u0, w2, v[2]);
            v[3] = fmaf(u1, w0, v[3]); v[4] = fmaf(u1, w1, v[4]); v[5] = fmaf(u1, w2, v[5]);
            v[6] = fmaf(u2, w0, v[6]); v[7] = fmaf(u2, w1, v[7]); v[8] = fmaf(u2, w2, v[8]);
            v[9]  = fmaf(u0, u0, fmaf(u1, u1, fmaf(u2, u2, v[9])));
            v[10] = fmaf(w0, w0, fmaf(w1, w1, fmaf(w2, w2, v[10])));
        }
    }

    // Warp butterfly reduction: all lanes end with the full batch sums
#pragma unroll
    for (int off = 16; off > 0; off >>= 1) {
#pragma unroll
        for (int i = 0; i < 11; i++)
            v[i] += __shfl_xor_sync(0xFFFFFFFFu, v[i], off);
    }

    // ---- Polar factor via determinant-scaled Newton (all lanes, redundant) ----
    float fro2 = 0.0f;
#pragma unroll
    for (int i = 0; i < 9; i++) fro2 = fmaf(v[i], v[i], fro2);
    const float invf = rsqrtf(fmaxf(fro2, 1e-30f));

    float X[9];
#pragma unroll
    for (int i = 0; i < 9; i++) X[i] = v[i] * invf;

#pragma unroll
    for (int it = 0; it < 8; it++) {
        float C[9];  // cofactor matrix: X^{-T} = C / det
        C[0] = X[4] * X[8] - X[5] * X[7];
        C[1] = X[5] * X[6] - X[3] * X[8];
        C[2] = X[3] * X[7] - X[4] * X[6];
        C[3] = X[2] * X[7] - X[1] * X[8];
        C[4] = X[0] * X[8] - X[2] * X[6];
        C[5] = X[1] * X[6] - X[0] * X[7];
        C[6] = X[1] * X[5] - X[2] * X[4];
        C[7] = X[2] * X[3] - X[0] * X[5];
        C[8] = X[0] * X[4] - X[1] * X[3];
        float det = X[0] * C[0] + X[1] * C[1] + X[2] * C[2];
        float ad  = fmaxf(fabsf(det), 1e-30f);
        float eta = rcbrtf(ad);            // |det|^{-1/3}
        float k1  = 0.5f * eta;
        float k2  = 0.5f / (eta * det);    // keeps det's sign
#pragma unroll
        for (int i = 0; i < 9; i++) X[i] = k1 * X[i] + k2 * C[i];
    }

    // t = mu_y - R mu_x
    const float t0 = my0 - (X[0] * mx0 + X[1] * mx1 + X[2] * mx2);
    const float t1 = my1 - (X[3] * mx0 + X[4] * mx1 + X[5] * mx2);
    const float t2 = my2 - (X[6] * mx0 + X[7] * mx1 + X[8] * mx2);

    const float sf = sqrtf(v[10]) / (sqrtf(v[9]) + 1e-6f);

    // ---- Coalesced predicated stores (select-chains, no reg-indexed arrays) ----
    if (lane < 9) {
        float r = (lane == 0) ? X[0] :
                  (lane == 1) ? X[1] :
                  (lane == 2) ? X[2] :
                  (lane == 3) ? X[3] :
                  (lane == 4) ? X[4] :
                  (lane == 5) ? X[5] :
                  (lane == 6) ? X[6] :
                  (lane == 7) ? X[7] : X[8];
        out[(size_t)b * 9 + lane] = r;
    }
    if (lane < 3) {
        float tv = (lane == 0) ? t0 : (lane == 1) ? t1 : t2;
        out[(size_t)B * 9 + (size_t)b * 3 + lane] = tv;
    }
    if (lane == 0) {
        out[(size_t)B * 12 + b] = sf;
    }
}

extern "C" void kernel_launch(void* const* d_in, const int* in_sizes, int n_in,
                              void* d_out, int out_size)
{
    const float* x    = (const float*)d_in[0];
    const float* mu_x = (const float*)d_in[1];
    const float* y    = (const float*)d_in[2];
    const float* mu_y = (const float*)d_in[3];
    float* out        = (float*)d_out;

    const int B = in_sizes[1] / 3;  // mu_x is [B,3]

    align9dof_kernel<<<(B + 7) / 8, 256>>>(x, mu_x, y, mu_y, out, B);
}